// round 4
// baseline (speedup 1.0000x reference)
#include <cuda_runtime.h>

// Problem constants (match reference exactly)
#define NN   50000   // nodes
#define HID  128     // hidden
#define NC   8       // classes
#define NS   5       // schemes
#define NK   16      // neighbors per scheme
#define TILE 32      // nodes per block-tile in stage 1
#define HS_PAD 132   // padded hs row (avoid 4-way bank conflicts in layer 2)
#define T1   256     // stage-1 block size

// Scratch: probs[n][c] = softmax(mlp(feats[n])). 1.6 MB -> lives in L2 for stage 2.
__device__ float g_probs[NN * NC];

constexpr int SMEM_FLOATS = HID*HID + HID*NC + HID + NC + TILE*HID + TILE*HS_PAD;
constexpr size_t SMEM_BYTES = (size_t)SMEM_FLOATS * sizeof(float);

// ---------------------------------------------------------------------------
// Stage 1: probs = softmax(relu(feats @ W1 + b1) @ W2 + b2)
// Block = 256 threads. W1 (64KB) cached in SMEM once per block, then
// grid-stride over 32-node tiles. Layer 1 register blocking:
//   thread (jt = tid&31, ng = tid>>5) computes 4 outputs (cols 4*jt..4*jt+3)
//   for 4 nodes (ng*4..ng*4+3): per k-step 1 LDS.128 (W) + 4 broadcast LDS (x)
//   feed 16 FFMA -> FFMA-pipe bound.
// Layer 2: one thread per (node, class) of the tile (32*8 = 256), then an
// 8-lane shfl softmax.
// ---------------------------------------------------------------------------
__global__ __launch_bounds__(T1, 2)
void mlp_probs_kernel(const float* __restrict__ feats,
                      const float* __restrict__ W1,
                      const float* __restrict__ b1,
                      const float* __restrict__ W2,
                      const float* __restrict__ b2,
                      int n_tiles)
{
    extern __shared__ float sm[];
    float* W1s = sm;                    // HID*HID
    float* W2s = W1s + HID*HID;         // HID*NC
    float* b1s = W2s + HID*NC;          // HID
    float* b2s = b1s + HID;             // NC
    float* xs  = b2s + NC;              // TILE*HID  (16B-aligned: offset 17544 floats)
    float* hs  = xs + TILE*HID;         // TILE*HS_PAD (16B-aligned: offset 21640 floats)

    const int tid = threadIdx.x;

    // Load weights/biases once per block
    for (int i = tid; i < HID*HID; i += T1) W1s[i] = W1[i];
    for (int i = tid; i < HID*NC;  i += T1) W2s[i] = W2[i];
    if (tid < HID) b1s[tid] = b1[tid];
    if (tid < NC)  b2s[tid] = b2[tid];
    __syncthreads();

    const int jt = tid & 31;    // column group: cols 4*jt .. 4*jt+3
    const int ng = tid >> 5;    // node group:  nodes ng*4 .. ng*4+3
    const int n2 = tid >> 3;    // layer-2 node within tile
    const int cc = tid & 7;     // layer-2 class

    for (int tile = blockIdx.x; tile < n_tiles; tile += gridDim.x) {
        const int node0 = tile * TILE;

        // Load 32 node feature rows (float4-coalesced); zero-pad past NN.
        for (int v = tid; v < TILE * (HID/4); v += T1) {
            const int n  = v >> 5;            // v / (HID/4)
            const int gn = node0 + n;
            float4 val = make_float4(0.f, 0.f, 0.f, 0.f);
            if (gn < NN)
                val = reinterpret_cast<const float4*>(feats)[(size_t)gn * (HID/4) + (v & 31)];
            reinterpret_cast<float4*>(xs)[v] = val;
        }
        __syncthreads();

        // -------- Layer 1: h = relu(x @ W1 + b1), 4x4 register block --------
        float acc[4][4];
        #pragma unroll
        for (int t = 0; t < 4; t++)
            #pragma unroll
            for (int j = 0; j < 4; j++) acc[t][j] = 0.f;

        const float* xb = xs + ng * 4 * HID;
        #pragma unroll 8
        for (int i = 0; i < HID; i++) {
            const float4 w = reinterpret_cast<const float4*>(W1s + i*HID)[jt];
            const float x0 = xb[i];
            const float x1 = xb[HID + i];
            const float x2 = xb[2*HID + i];
            const float x3 = xb[3*HID + i];
            acc[0][0] += x0*w.x; acc[0][1] += x0*w.y; acc[0][2] += x0*w.z; acc[0][3] += x0*w.w;
            acc[1][0] += x1*w.x; acc[1][1] += x1*w.y; acc[1][2] += x1*w.z; acc[1][3] += x1*w.w;
            acc[2][0] += x2*w.x; acc[2][1] += x2*w.y; acc[2][2] += x2*w.z; acc[2][3] += x2*w.w;
            acc[3][0] += x3*w.x; acc[3][1] += x3*w.y; acc[3][2] += x3*w.z; acc[3][3] += x3*w.w;
        }

        const float4 bv = reinterpret_cast<const float4*>(b1s)[jt];
        #pragma unroll
        for (int t = 0; t < 4; t++) {
            float4 hv;
            hv.x = fmaxf(acc[t][0] + bv.x, 0.f);
            hv.y = fmaxf(acc[t][1] + bv.y, 0.f);
            hv.z = fmaxf(acc[t][2] + bv.z, 0.f);
            hv.w = fmaxf(acc[t][3] + bv.w, 0.f);
            *reinterpret_cast<float4*>(hs + (ng*4 + t)*HS_PAD + 4*jt) = hv;
        }
        __syncthreads();

        // -------- Layer 2 + softmax: one thread per (node, class) --------
        float o = b2s[cc];
        const float* hr = hs + n2 * HS_PAD;
        #pragma unroll 8
        for (int j = 0; j < HID; j++)
            o += hr[j] * W2s[j*NC + cc];

        // softmax over 8 classes: lanes (8c per node) are contiguous in the warp
        float m = o;
        #pragma unroll
        for (int d = 1; d < NC; d <<= 1)
            m = fmaxf(m, __shfl_xor_sync(0xffffffffu, m, d));
        const float e = __expf(o - m);
        float ssum = e;
        #pragma unroll
        for (int d = 1; d < NC; d <<= 1)
            ssum += __shfl_xor_sync(0xffffffffu, ssum, d);

        const int gn = node0 + n2;
        if (gn < NN)
            g_probs[gn*NC + cc] = e / ssum;
        __syncthreads();   // protect xs/hs before next tile
    }
}

// ---------------------------------------------------------------------------
// Stage 2: gather/aggregate. 8 threads per node (one per class).
// Per node: 5*16 = 80 gathers of probs rows; the 8 lanes of a node coalesce
// each gather into a single 32B L2 sector. probs (1.6MB) stays L2-resident.
// ---------------------------------------------------------------------------
__global__ __launch_bounds__(256)
void aggregate_kernel(const int* __restrict__ nei,
                      const float* __restrict__ attention,
                      const float* __restrict__ alpha,
                      float* __restrict__ out)
{
    const int t = blockIdx.x * blockDim.x + threadIdx.x;
    const int n = t >> 3;
    const int c = t & 7;
    if (n >= NN) return;

    // softmax over the 5 scheme-attention logits (broadcast loads, L1-hit)
    float a[NS];
    #pragma unroll
    for (int s = 0; s < NS; s++) a[s] = attention[n*NS + s];
    float m = a[0];
    #pragma unroll
    for (int s = 1; s < NS; s++) m = fmaxf(m, a[s]);
    float asum = 0.f;
    #pragma unroll
    for (int s = 0; s < NS; s++) { a[s] = __expf(a[s] - m); asum += a[s]; }
    const float inv_asum = 1.f / asum;

    float acc = 0.f;
    #pragma unroll
    for (int s = 0; s < NS; s++) {
        const int* nb = nei + ((size_t)s * NN + n) * NK;
        float sacc = 0.f;
        #pragma unroll
        for (int k = 0; k < NK; k++) {
            const int idx = __ldg(&nb[k]);
            sacc += g_probs[idx*NC + c];
        }
        acc += (a[s] * inv_asum) * sacc;
    }
    acc *= (1.f / (float)NK);

    const float g = 1.f / (1.f + __expf(-alpha[n]));
    out[n*NC + c] = g * g_probs[n*NC + c] + (1.f - g) * acc;
}

// ---------------------------------------------------------------------------
// Launch. Inputs (metadata order): sc_nei i32[5*50000*16], feats f32[50000*128],
// W1 f32[128*128], b1 f32[128], W2 f32[128*8], b2 f32[8], alpha f32[50000],
// attention f32[50000*5]. Output f32[50000*8].
// ---------------------------------------------------------------------------
extern "C" void kernel_launch(void* const* d_in, const int* in_sizes, int n_in,
                              void* d_out, int out_size)
{
    const int*   sc_nei    = (const int*)  d_in[0];
    const float* feats     = (const float*)d_in[1];
    const float* W1        = (const float*)d_in[2];
    const float* b1        = (const float*)d_in[3];
    const float* W2        = (const float*)d_in[4];
    const float* b2        = (const float*)d_in[5];
    const float* alpha     = (const float*)d_in[6];
    const float* attention = (const float*)d_in[7];
    float*       out       = (float*)d_out;

    cudaFuncSetAttribute(mlp_probs_kernel,
                         cudaFuncAttributeMaxDynamicSharedMemorySize,
                         (int)SMEM_BYTES);

    const int n_tiles = (NN + TILE - 1) / TILE;            // 1563
    mlp_probs_kernel<<<304, T1, SMEM_BYTES>>>(feats, W1, b1, W2, b2, n_tiles);

    const int agg_threads = NN * NC;                       // 400000
    aggregate_kernel<<<(agg_threads + 255) / 256, 256>>>(sc_nei, attention, alpha, out);
}